// round 3
// baseline (speedup 1.0000x reference)
#include <cuda_runtime.h>
#include <cstdint>

// Problem constants
#define B_      32
#define CIN     64
#define COUT    64
#define HH      56
#define WW      56
#define LL      3136          // 56*56
#define FEAT    576           // 64*3*3

#define NTHREADS      192     // 6 warps, k-split over f
#define NWARPS        6
#define CHUNK_F       48      // f per weight chunk
#define NCHUNK        12      // 576/48
#define FQC           12      // float4 columns per chunk
#define FQ_PER_WARP   2       // 12 fq / 6 warps

// patch: [32][144] float4 = 73728 B (no pad needed: patch LDS are broadcast)
#define PATCH_F4      144
#define PATCH_BYTES   (B_ * PATCH_F4 * 16)
// weight ring: [2][12 fq][64 c] float4 = 24576 B
#define WBUF_BYTES    (FQC * COUT * 16)
#define SMEM_W_OFF    PATCH_BYTES
#define SMEM_TOTAL    (PATCH_BYTES + 2 * WBUF_BYTES)   // 98304

using ull = unsigned long long;
struct U2 { ull lo, hi; };

__device__ __forceinline__ U2 lds128(uint32_t addr) {
    U2 r;
    asm volatile("ld.shared.v2.u64 {%0, %1}, [%2];"
                 : "=l"(r.lo), "=l"(r.hi) : "r"(addr));
    return r;
}

__device__ __forceinline__ void fma2(ull& acc, ull a, ull b) {
    asm("fma.rn.f32x2 %0, %1, %2, %0;" : "+l"(acc) : "l"(a), "l"(b));
}

__device__ __forceinline__ float hsum2(ull v) {
    float lo, hi;
    asm("mov.b64 {%0, %1}, %2;" : "=f"(lo), "=f"(hi) : "l"(v));
    return lo + hi;
}

__device__ __forceinline__ void cp_async16(uint32_t smem_addr, const void* gmem_ptr) {
    asm volatile("cp.async.cg.shared.global [%0], [%1], 16;\n"
                 :: "r"(smem_addr), "l"(gmem_ptr));
}

__global__ void __launch_bounds__(NTHREADS, 2)
lc2d_kernel(const float* __restrict__ x,
            const float* __restrict__ w,
            const float* __restrict__ bias,
            float* __restrict__ out)
{
    extern __shared__ char smem[];
    float* ps = (float*)smem;                          // patch [32][576] floats
    const uint32_t sbase = (uint32_t)__cvta_generic_to_shared(smem);
    const uint32_t wsmem = sbase + SMEM_W_OFF;

    const int tid  = threadIdx.x;
    const int lane = tid & 31;
    const int warp = tid >> 5;
    const int l    = blockIdx.x;
    const int oh   = l / WW;
    const int ow   = l - oh * WW;

    const float* wl = w + (size_t)l * (COUT * FEAT);

    // ---- weight cp.async mapping: 768 f4/chunk, 4 per thread ----
    // e = tid + 192*j ; fq = e % 12 ; c = e / 12 ; smem [fq][c]
    const float* wg[4];
    uint32_t wsd[4];
    #pragma unroll
    for (int j = 0; j < 4; j++) {
        int e  = tid + NTHREADS * j;
        int fq = e % FQC;
        int c  = e / FQC;
        wg[j]  = wl + (size_t)c * FEAT + 4 * fq;
        wsd[j] = wsmem + (uint32_t)(fq * COUT + c) * 16;
    }

    // ---- issue weight chunk 0 (buf 0) ----
    #pragma unroll
    for (int j = 0; j < 4; j++) cp_async16(wsd[j], wg[j]);
    asm volatile("cp.async.commit_group;\n");

    // ---- stage patch tile (overlaps chunk-0 arrival) ----
    for (int f = tid; f < FEAT; f += NTHREADS) {
        int cin = f / 9;
        int r   = f - cin * 9;
        int ki  = r / 3;
        int kj  = r - ki * 3;
        int h   = oh + ki - 1;
        int wc  = ow + kj - 1;
        bool ok = ((unsigned)h < HH) & ((unsigned)wc < WW);
        const float* xp = x + ((size_t)cin * HH + h) * WW + wc;
        float* pp = ps + f;
        #pragma unroll 8
        for (int b = 0; b < B_; b++) {
            float v = ok ? xp[(size_t)b * (CIN * HH * WW)] : 0.0f;
            pp[b * FEAT] = v;
        }
    }

    // lane mapping: 4 batch-groups x 8 channel-groups; thread tile 8b x 8c
    const int bg = lane >> 3;          // b = bg*8 + i
    const int cg = lane & 7;           // c = cg + 8*j

    // per-thread smem addresses
    const uint32_t paddr = sbase + (uint32_t)(bg * 8 * PATCH_F4) * 16;   // + i*2304 + fqa*16
    const uint32_t waddr = wsmem + (uint32_t)(warp * FQ_PER_WARP * COUT + cg) * 16; // + t*1024 + j*128

    ull acc[64];
    #pragma unroll
    for (int i = 0; i < 64; i++) acc[i] = 0ull;

    for (int k = 0; k < NCHUNK; k++) {
        if (k + 1 < NCHUNK) {
            const int f0 = (k + 1) * CHUNK_F;
            const uint32_t bufoff = (uint32_t)(((k + 1) & 1) * WBUF_BYTES);
            #pragma unroll
            for (int j = 0; j < 4; j++) cp_async16(wsd[j] + bufoff, wg[j] + f0);
            asm volatile("cp.async.commit_group;\n");
            asm volatile("cp.async.wait_group 1;\n");
        } else {
            asm volatile("cp.async.wait_group 0;\n");
        }
        __syncthreads();

        const uint32_t wb = waddr + (uint32_t)((k & 1) * WBUF_BYTES);
        const uint32_t pb = paddr + (uint32_t)((k * FQC + warp * FQ_PER_WARP) * 16);

        #pragma unroll
        for (int t = 0; t < FQ_PER_WARP; t++) {
            U2 wv[8];
            #pragma unroll
            for (int j = 0; j < 8; j++)
                wv[j] = lds128(wb + (uint32_t)t * (COUT * 16) + j * 128);
            #pragma unroll
            for (int i = 0; i < 8; i++) {
                U2 pv = lds128(pb + (uint32_t)t * 16 + (uint32_t)i * (PATCH_F4 * 16));
                #pragma unroll
                for (int j = 0; j < 8; j++) {
                    fma2(acc[i * 8 + j], pv.lo, wv[j].lo);
                    fma2(acc[i * 8 + j], pv.hi, wv[j].hi);
                }
            }
        }
        __syncthreads();
    }

    // ---- cross-warp k-reduction via smem (reuse patch area) ----
    float* red = (float*)smem;   // [6 warps][32 b][64 c]
    #pragma unroll
    for (int i = 0; i < 8; i++) {
        #pragma unroll
        for (int j = 0; j < 8; j++) {
            int b = bg * 8 + i;
            int c = cg + 8 * j;
            red[warp * 2048 + b * 64 + c] = hsum2(acc[i * 8 + j]);
        }
    }
    __syncthreads();

    const float* bl = bias + (size_t)l * COUT;
    for (int o = tid; o < 2048; o += NTHREADS) {
        float s = red[o];
        #pragma unroll
        for (int wq = 1; wq < NWARPS; wq++) s += red[wq * 2048 + o];
        int b = o >> 6;
        int c = o & 63;
        out[((size_t)(b * COUT) + c) * LL + l] = s + bl[c];
    }
}

extern "C" void kernel_launch(void* const* d_in, const int* in_sizes, int n_in,
                              void* d_out, int out_size)
{
    const float* x    = (const float*)d_in[0];   // [32,64,56,56]
    const float* w    = (const float*)d_in[1];   // [3136,64,576]
    const float* bias = (const float*)d_in[2];   // [3136,64]
    float* out        = (float*)d_out;           // [32,64,56,56]

    cudaFuncSetAttribute(lc2d_kernel, cudaFuncAttributeMaxDynamicSharedMemorySize, SMEM_TOTAL);
    lc2d_kernel<<<LL, NTHREADS, SMEM_TOTAL>>>(x, w, bias, out);
}

// round 5
// speedup vs baseline: 1.6201x; 1.6201x over previous
#include <cuda_runtime.h>
#include <cstdint>

#define BATCH   32
#define CIN     64
#define COUT    64
#define HH      56
#define WW      56
#define LL      3136
#define FEAT    576
#define NCHUNK  18            // 576 / 32 f per chunk
#define NTHREADS 128

// ---- smem layout ----
// patch: [32 b][580 floats] (tf32 bits), row = 2320 B (odd multiple of 16 ->
//        consecutive rows rotate 16B bank groups -> ldmatrix conflict-free)
#define PROW_FLOATS 580
#define PROW_BYTES  (PROW_FLOATS * 4)          // 2320
#define PATCH_BYTES (BATCH * PROW_BYTES)       // 74240
// weight tiles: 2 x [64 c][32 f] fp32 (SW128-swizzled rows of 128B)
#define WTILE_BYTES 8192
#define WT_OFF      PATCH_BYTES
#define SMEM_TOTAL  (WT_OFF + 2 * WTILE_BYTES) // 90624

// scratch: x transposed to [B][H*W][C]
__device__ float g_xt[(size_t)BATCH * LL * CIN];

// ---------------- helpers ----------------
__device__ __forceinline__ uint32_t swz(uint32_t o) { return o ^ ((o >> 3) & 0x70); }

__device__ __forceinline__ uint32_t cvt_tf32(float v) {
    uint32_t t;
    asm("cvt.rna.tf32.f32 %0, %1;" : "=r"(t) : "f"(v));
    return t;
}

__device__ __forceinline__ void sts128(uint32_t a, uint32_t x, uint32_t y, uint32_t z, uint32_t w) {
    asm volatile("st.shared.v4.b32 [%0], {%1,%2,%3,%4};"
                 :: "r"(a), "r"(x), "r"(y), "r"(z), "r"(w) : "memory");
}
__device__ __forceinline__ void sts32(uint32_t a, uint32_t v) {
    asm volatile("st.shared.b32 [%0], %1;" :: "r"(a), "r"(v) : "memory");
}

__device__ __forceinline__ void ldsm_x4(uint32_t addr, uint32_t& r0, uint32_t& r1,
                                        uint32_t& r2, uint32_t& r3) {
    asm volatile("ldmatrix.sync.aligned.m8n8.x4.shared.b16 {%0,%1,%2,%3}, [%4];"
                 : "=r"(r0), "=r"(r1), "=r"(r2), "=r"(r3) : "r"(addr));
}

__device__ __forceinline__ void mma_tf32(float* d, const uint32_t* a, const uint32_t* b) {
    asm volatile("mma.sync.aligned.m16n8k8.row.col.f32.tf32.tf32.f32 "
                 "{%0,%1,%2,%3}, {%4,%5,%6,%7}, {%8,%9}, {%0,%1,%2,%3};"
                 : "+f"(d[0]), "+f"(d[1]), "+f"(d[2]), "+f"(d[3])
                 : "r"(a[0]), "r"(a[1]), "r"(a[2]), "r"(a[3]),
                   "r"(b[0]), "r"(b[1]));
}

// ---------------- kernel 1: x NCHW -> NHWC transpose ----------------
__global__ void __launch_bounds__(256) transpose_x(const float* __restrict__ x) {
    __shared__ float tile[32][33];
    const int b  = blockIdx.z;
    const int c0 = blockIdx.y * 32;
    const int s0 = blockIdx.x * 32;
    const int tx = threadIdx.x & 31;
    const int ty = threadIdx.x >> 5;   // 0..7
    #pragma unroll
    for (int i = 0; i < 4; i++)
        tile[ty + 8 * i][tx] = x[((size_t)b * CIN + c0 + ty + 8 * i) * LL + s0 + tx];
    __syncthreads();
    #pragma unroll
    for (int i = 0; i < 4; i++)
        g_xt[((size_t)b * LL + s0 + ty + 8 * i) * CIN + c0 + tx] = tile[tx][ty + 8 * i];
}

// ---------------- kernel 2: per-location GEMM via mma.sync tf32 ----------------
__global__ void __launch_bounds__(NTHREADS, 2)
lc2d_mma(const float* __restrict__ w,
         const float* __restrict__ bias,
         float* __restrict__ out)
{
    extern __shared__ char smem[];
    const uint32_t sb = (uint32_t)__cvta_generic_to_shared(smem);

    const int tid  = threadIdx.x;
    const int lane = tid & 31;
    const int warp = tid >> 5;
    const int l    = blockIdx.x;
    const int oh   = l / WW;
    const int ow   = l - oh * WW;

    const float* wl = w + (size_t)l * (COUT * FEAT);

    // ---- weight LDG mapping: thread -> channel c, f4 slots g = fsel + 2j ----
    const int wc   = tid >> 1;        // 0..63
    const int fsel = tid & 1;
    const float* wg = wl + (size_t)wc * FEAT + 4 * fsel;
    const uint32_t wst_base = sb + WT_OFF;   // + buf*8192 + swz(c*128 + g*16)

    // prefetch chunks 0,1 into registers
    float4 r[2][4];
    #pragma unroll
    for (int j = 0; j < 4; j++) r[0][j] = *(const float4*)(wg + 8 * j);
    #pragma unroll
    for (int j = 0; j < 4; j++) r[1][j] = *(const float4*)(wg + 32 + 8 * j);

    // ---- stage patches from g_xt (NHWC): segment = (b, ki, kj), 16 thr/seg ----
    {
        const int pos = tid & 15;                 // cin group: cin = pos*4 + q
        for (int s = tid >> 4; s < BATCH * 9; s += 8) {
            int b  = s / 9;
            int rr = s - b * 9;                   // ki*3 + kj
            int ki = rr / 3, kj = rr - ki * 3;
            int h  = oh + ki - 1;
            int wq = ow + kj - 1;
            bool ok = ((unsigned)h < HH) & ((unsigned)wq < WW);
            float4 v = make_float4(0.f, 0.f, 0.f, 0.f);
            if (ok)
                v = *(const float4*)(g_xt + ((size_t)b * LL + h * WW + wq) * CIN + pos * 4);
            const uint32_t prow = sb + (uint32_t)b * PROW_BYTES;
            #pragma unroll
            for (int q = 0; q < 4; q++) {
                float val = (q == 0) ? v.x : (q == 1) ? v.y : (q == 2) ? v.z : v.w;
                int f = (pos * 4 + q) * 9 + rr;
                sts32(prow + (uint32_t)f * 4, cvt_tf32(val));
            }
        }
    }

    // ---- per-warp fragment addressing ----
    // warp tile: channels c0w..c0w+31 (2 m-tiles), batches b0w..b0w+15 (2 n-tiles)
    const int c0w = (warp & 1) * 32;
    const int b0w = (warp >> 1) * 16;

    // A ldmatrix lane address (per m-tile): row = c0w + mi*16 + (lane&15),
    // col byte = ks*32 + ((lane&16) ? 16 : 0); swizzled within 128B row.
    const uint32_t a_row  = (uint32_t)(c0w + (lane & 15));
    const uint32_t a_colq = (lane & 16) ? 16u : 0u;
    // B ldmatrix lane address: row = b0w + (lane&7) + ((lane&16)?8:0),
    // col byte = k*128 + ks*32 + (((lane>>3)&1)?16:0)
    const uint32_t b_row  = (uint32_t)(b0w + (lane & 7) + ((lane & 16) ? 8 : 0));
    const uint32_t b_colq = ((lane >> 3) & 1) ? 16u : 0u;
    const uint32_t b_base = sb + b_row * PROW_BYTES + b_colq;

    float acc[2][2][4];
    #pragma unroll
    for (int mi = 0; mi < 2; mi++)
        #pragma unroll
        for (int ni = 0; ni < 2; ni++)
            #pragma unroll
            for (int q = 0; q < 4; q++) acc[mi][ni][q] = 0.0f;

    __syncthreads();   // patch tile ready

    for (int k = 0; k < NCHUNK; k++) {
        const int buf = k & 1;
        // stage weight chunk k: cvt + STS (8 float4 per thread-pair row)
        const uint32_t wt = wst_base + (uint32_t)buf * WTILE_BYTES;
        #pragma unroll
        for (int j = 0; j < 4; j++) {
            const int g = fsel + 2 * j;
            sts128(wt + swz((uint32_t)(wc * 128 + g * 16)),
                   cvt_tf32(r[buf][j].x), cvt_tf32(r[buf][j].y),
                   cvt_tf32(r[buf][j].z), cvt_tf32(r[buf][j].w));
        }
        // prefetch chunk k+2 into the freed register set
        if (k + 2 < NCHUNK) {
            #pragma unroll
            for (int j = 0; j < 4; j++)
                r[buf][j] = *(const float4*)(wg + (k + 2) * 32 + 8 * j);
        }
        __syncthreads();   // tile[buf] visible; also protects against overwrite

        // ---- compute chunk k: 4 k-steps of 8 f ----
        #pragma unroll
        for (int ks = 0; ks < 4; ks++) {
            uint32_t a0[4], a1[4], bfr[4];
            const uint32_t acol = (uint32_t)ks * 32 + a_colq;
            ldsm_x4(wt + swz(a_row * 128 + acol),              a0[0], a0[1], a0[2], a0[3]);
            ldsm_x4(wt + swz((a_row + 16) * 128 + acol),       a1[0], a1[1], a1[2], a1[3]);
            ldsm_x4(b_base + (uint32_t)(k * 128 + ks * 32),    bfr[0], bfr[1], bfr[2], bfr[3]);
            mma_tf32(acc[0][0], a0, bfr);       // b-regs {0,1} = n-tile 0
            mma_tf32(acc[0][1], a0, bfr + 2);   // b-regs {2,3} = n-tile 1
            mma_tf32(acc[1][0], a1, bfr);
            mma_tf32(acc[1][1], a1, bfr + 2);
        }
        __syncthreads();
    }

    // ---- epilogue ----
    // d mapping: c0:(g,2t) c1:(g,2t+1) c2:(g+8,2t) c3:(g+8,2t+1), g=lane>>2, t=lane&3
    const int g  = lane >> 2;
    const int t  = lane & 3;
    const float* bl = bias + (size_t)l * COUT;
    #pragma unroll
    for (int mi = 0; mi < 2; mi++) {
        const int chA = c0w + mi * 16 + g;
        const float bvA = bl[chA];
        const float bvB = bl[chA + 8];
        #pragma unroll
        for (int ni = 0; ni < 2; ni++) {
            const int b0 = b0w + ni * 8 + 2 * t;
            out[((size_t)((b0    ) * COUT) + chA    ) * LL + l] = acc[mi][ni][0] + bvA;
            out[((size_t)((b0 + 1) * COUT) + chA    ) * LL + l] = acc[mi][ni][1] + bvA;
            out[((size_t)((b0    ) * COUT) + chA + 8) * LL + l] = acc[mi][ni][2] + bvB;
            out[((size_t)((b0 + 1) * COUT) + chA + 8) * LL + l] = acc[mi][ni][3] + bvB;
        }
    }
}

extern "C" void kernel_launch(void* const* d_in, const int* in_sizes, int n_in,
                              void* d_out, int out_size)
{
    const float* x    = (const float*)d_in[0];   // [32,64,56,56]
    const float* w    = (const float*)d_in[1];   // [3136,64,576]
    const float* bias = (const float*)d_in[2];   // [3136,64]
    float* out        = (float*)d_out;           // [32,64,56,56]

    transpose_x<<<dim3(LL / 32, CIN / 32, BATCH), 256>>>(x);

    cudaFuncSetAttribute(lc2d_mma, cudaFuncAttributeMaxDynamicSharedMemorySize, SMEM_TOTAL);
    lc2d_mma<<<LL, NTHREADS, SMEM_TOTAL>>>(w, bias, out);
}

// round 6
// speedup vs baseline: 2.5646x; 1.5830x over previous
#include <cuda_runtime.h>
#include <cstdint>

#define BATCH   32
#define CIN     64
#define COUT    64
#define HH      56
#define WW      56
#define LL      3136
#define FEAT    576
#define NCHUNK  18            // 576 / 32 f per chunk
#define NTHREADS 128
#define NSTAGE  4

// ---- smem layout ----
// patch: [32 b][580 floats] (tf32 bits), row = 2320 B (odd multiple of 16 ->
//        consecutive rows rotate 16B bank groups -> ldmatrix conflict-free)
#define PROW_FLOATS 580
#define PROW_BYTES  (PROW_FLOATS * 4)          // 2320
#define PATCH_BYTES (BATCH * PROW_BYTES)       // 74240
// weight ring: 4 x [64 c][32 f] raw fp32 (SW128-swizzled 128B rows)
#define WTILE_BYTES 8192
#define WT_OFF      PATCH_BYTES
#define SMEM_TOTAL  (WT_OFF + NSTAGE * WTILE_BYTES)   // 107008

// scratch: x transposed to [B][H*W][C]
__device__ float g_xt[(size_t)BATCH * LL * CIN];

// ---------------- helpers ----------------
__device__ __forceinline__ uint32_t swz(uint32_t o) { return o ^ ((o >> 3) & 0x70); }

__device__ __forceinline__ uint32_t cvt_tf32(float v) {
    uint32_t t;
    asm("cvt.rna.tf32.f32 %0, %1;" : "=r"(t) : "f"(v));
    return t;
}
__device__ __forceinline__ uint32_t tf32r(uint32_t bits) {
    uint32_t t;
    asm("cvt.rna.tf32.f32 %0, %1;" : "=r"(t) : "f"(__uint_as_float(bits)));
    return t;
}

__device__ __forceinline__ void sts32(uint32_t a, uint32_t v) {
    asm volatile("st.shared.b32 [%0], %1;" :: "r"(a), "r"(v) : "memory");
}

__device__ __forceinline__ void cp_async16(uint32_t smem_addr, const void* gmem_ptr) {
    asm volatile("cp.async.cg.shared.global [%0], [%1], 16;\n"
                 :: "r"(smem_addr), "l"(gmem_ptr));
}

__device__ __forceinline__ void ldsm_x4(uint32_t addr, uint32_t& r0, uint32_t& r1,
                                        uint32_t& r2, uint32_t& r3) {
    asm volatile("ldmatrix.sync.aligned.m8n8.x4.shared.b16 {%0,%1,%2,%3}, [%4];"
                 : "=r"(r0), "=r"(r1), "=r"(r2), "=r"(r3) : "r"(addr));
}

__device__ __forceinline__ void mma_tf32(float* d, const uint32_t* a, const uint32_t* b) {
    asm volatile("mma.sync.aligned.m16n8k8.row.col.f32.tf32.tf32.f32 "
                 "{%0,%1,%2,%3}, {%4,%5,%6,%7}, {%8,%9}, {%0,%1,%2,%3};"
                 : "+f"(d[0]), "+f"(d[1]), "+f"(d[2]), "+f"(d[3])
                 : "r"(a[0]), "r"(a[1]), "r"(a[2]), "r"(a[3]),
                   "r"(b[0]), "r"(b[1]));
}

// ---------------- kernel 1: x NCHW -> NHWC transpose ----------------
__global__ void __launch_bounds__(256) transpose_x(const float* __restrict__ x) {
    __shared__ float tile[32][33];
    const int b  = blockIdx.z;
    const int c0 = blockIdx.y * 32;
    const int s0 = blockIdx.x * 32;
    const int tx = threadIdx.x & 31;
    const int ty = threadIdx.x >> 5;   // 0..7
    #pragma unroll
    for (int i = 0; i < 4; i++)
        tile[ty + 8 * i][tx] = x[((size_t)b * CIN + c0 + ty + 8 * i) * LL + s0 + tx];
    __syncthreads();
    #pragma unroll
    for (int i = 0; i < 4; i++)
        g_xt[((size_t)b * LL + s0 + ty + 8 * i) * CIN + c0 + tx] = tile[tx][ty + 8 * i];
}

// ---------------- kernel 2: per-location GEMM via mma.sync tf32 ----------------
__global__ void __launch_bounds__(NTHREADS, 2)
lc2d_mma(const float* __restrict__ w,
         const float* __restrict__ bias,
         float* __restrict__ out)
{
    extern __shared__ char smem[];
    const uint32_t sb = (uint32_t)__cvta_generic_to_shared(smem);
    const uint32_t wst_base = sb + WT_OFF;

    const int tid  = threadIdx.x;
    const int lane = tid & 31;
    const int warp = tid >> 5;
    const int l    = blockIdx.x;
    const int oh   = l / WW;
    const int ow   = l - oh * WW;

    const float* wl = w + (size_t)l * (COUT * FEAT);

    // ---- weight cp.async mapping: thread -> channel wc, f4 slots g = fsel + 2j ----
    const int wc   = tid >> 1;        // 0..63
    const int fsel = tid & 1;
    const float* wg = wl + (size_t)wc * FEAT + 4 * fsel;   // + k*32 + 8j
    const uint32_t wsd = (uint32_t)wc * 128 + (uint32_t)fsel * 16;  // + j*32 (pre-swz)

    // ---- prologue: issue weight chunks 0..2 into stages 0..2 ----
    #pragma unroll
    for (int k = 0; k < NSTAGE - 1; k++) {
        const uint32_t st = wst_base + (uint32_t)k * WTILE_BYTES;
        #pragma unroll
        for (int j = 0; j < 4; j++)
            cp_async16(st + swz(wsd + (uint32_t)j * 32), wg + k * 32 + 8 * j);
        asm volatile("cp.async.commit_group;\n");
    }

    // ---- stage patches from g_xt (NHWC): segment = (b, ki, kj), 16 thr/seg ----
    {
        const int pos = tid & 15;                 // cin group: cin = pos*4 + q
        for (int s = tid >> 4; s < BATCH * 9; s += 8) {
            int b  = s / 9;
            int rr = s - b * 9;                   // ki*3 + kj
            int ki = rr / 3, kj = rr - ki * 3;
            int h  = oh + ki - 1;
            int wq = ow + kj - 1;
            bool ok = ((unsigned)h < HH) & ((unsigned)wq < WW);
            float4 v = make_float4(0.f, 0.f, 0.f, 0.f);
            if (ok)
                v = *(const float4*)(g_xt + ((size_t)b * LL + h * WW + wq) * CIN + pos * 4);
            const uint32_t prow = sb + (uint32_t)b * PROW_BYTES;
            #pragma unroll
            for (int q = 0; q < 4; q++) {
                float val = (q == 0) ? v.x : (q == 1) ? v.y : (q == 2) ? v.z : v.w;
                int f = (pos * 4 + q) * 9 + rr;
                sts32(prow + (uint32_t)f * 4, cvt_tf32(val));
            }
        }
    }

    // ---- per-warp fragment addressing ----
    const int c0w = (warp & 1) * 32;
    const int b0w = (warp >> 1) * 16;

    const uint32_t a_row  = (uint32_t)(c0w + (lane & 15));
    const uint32_t a_colq = (lane & 16) ? 16u : 0u;
    const uint32_t b_row  = (uint32_t)(b0w + (lane & 7) + ((lane & 16) ? 8 : 0));
    const uint32_t b_colq = ((lane >> 3) & 1) ? 16u : 0u;
    const uint32_t b_base = sb + b_row * PROW_BYTES + b_colq;

    float acc[2][2][4];
    #pragma unroll
    for (int mi = 0; mi < 2; mi++)
        #pragma unroll
        for (int ni = 0; ni < 2; ni++)
            #pragma unroll
            for (int q = 0; q < 4; q++) acc[mi][ni][q] = 0.0f;

    // ---- main loop: one barrier per chunk ----
    for (int k = 0; k < NCHUNK; k++) {
        // wait for chunk k's cp.async data (own copies), then publish
        if (k < NCHUNK - 2)      asm volatile("cp.async.wait_group 2;\n");
        else if (k == NCHUNK - 2) asm volatile("cp.async.wait_group 1;\n");
        else                      asm volatile("cp.async.wait_group 0;\n");
        __syncthreads();   // stage k visible to all; compute(k-1) fully drained

        // issue chunk k+3 into stage (k+3)%4  (safe: barrier above)
        if (k + NSTAGE - 1 < NCHUNK) {
            const uint32_t st = wst_base + (uint32_t)((k + NSTAGE - 1) & (NSTAGE - 1)) * WTILE_BYTES;
            const int f0 = (k + NSTAGE - 1) * 32;
            #pragma unroll
            for (int j = 0; j < 4; j++)
                cp_async16(st + swz(wsd + (uint32_t)j * 32), wg + f0 + 8 * j);
            asm volatile("cp.async.commit_group;\n");
        }

        // ---- compute chunk k from stage k%4 ----
        const uint32_t wt = wst_base + (uint32_t)(k & (NSTAGE - 1)) * WTILE_BYTES;
        #pragma unroll
        for (int ks = 0; ks < 4; ks++) {
            uint32_t a0[4], a1[4], bfr[4];
            const uint32_t acol = (uint32_t)ks * 32 + a_colq;
            ldsm_x4(wt + swz(a_row * 128 + acol),        a0[0], a0[1], a0[2], a0[3]);
            ldsm_x4(wt + swz((a_row + 16) * 128 + acol), a1[0], a1[1], a1[2], a1[3]);
            ldsm_x4(b_base + (uint32_t)(k * 128 + ks * 32), bfr[0], bfr[1], bfr[2], bfr[3]);
            #pragma unroll
            for (int q = 0; q < 4; q++) { a0[q] = tf32r(a0[q]); a1[q] = tf32r(a1[q]); }
            mma_tf32(acc[0][0], a0, bfr);
            mma_tf32(acc[0][1], a0, bfr + 2);
            mma_tf32(acc[1][0], a1, bfr);
            mma_tf32(acc[1][1], a1, bfr + 2);
        }
    }

    // ---- epilogue ----
    const int g  = lane >> 2;
    const int t  = lane & 3;
    const float* bl = bias + (size_t)l * COUT;
    #pragma unroll
    for (int mi = 0; mi < 2; mi++) {
        const int chA = c0w + mi * 16 + g;
        const float bvA = bl[chA];
        const float bvB = bl[chA + 8];
        #pragma unroll
        for (int ni = 0; ni < 2; ni++) {
            const int b0 = b0w + ni * 8 + 2 * t;
            out[((size_t)((b0    ) * COUT) + chA    ) * LL + l] = acc[mi][ni][0] + bvA;
            out[((size_t)((b0 + 1) * COUT) + chA    ) * LL + l] = acc[mi][ni][1] + bvA;
            out[((size_t)((b0    ) * COUT) + chA + 8) * LL + l] = acc[mi][ni][2] + bvB;
            out[((size_t)((b0 + 1) * COUT) + chA + 8) * LL + l] = acc[mi][ni][3] + bvB;
        }
    }
}

extern "C" void kernel_launch(void* const* d_in, const int* in_sizes, int n_in,
                              void* d_out, int out_size)
{
    const float* x    = (const float*)d_in[0];   // [32,64,56,56]
    const float* w    = (const float*)d_in[1];   // [3136,64,576]
    const float* bias = (const float*)d_in[2];   // [3136,64]
    float* out        = (float*)d_out;           // [32,64,56,56]

    transpose_x<<<dim3(LL / 32, CIN / 32, BATCH), 256>>>(x);

    cudaFuncSetAttribute(lc2d_mma, cudaFuncAttributeMaxDynamicSharedMemorySize, SMEM_TOTAL);
    lc2d_mma<<<LL, NTHREADS, SMEM_TOTAL>>>(w, bias, out);
}

// round 7
// speedup vs baseline: 2.8414x; 1.1079x over previous
#include <cuda_runtime.h>
#include <cstdint>

#define BATCH   32
#define CIN     64
#define COUT    64
#define HH      56
#define WW      56
#define LL      3136
#define FEAT    576
#define NCHUNK  18            // 576 / 32 f per chunk
#define NTHREADS 128
#define NSTAGE  4

// ---- smem layout ----
// patch: [32 b][580 floats] (tf32 bits), row = 2320 B (odd multiple of 16 ->
//        consecutive rows rotate 16B bank groups -> ldmatrix conflict-free)
#define PROW_FLOATS 580
#define PROW_BYTES  (PROW_FLOATS * 4)          // 2320
#define PATCH_BYTES (BATCH * PROW_BYTES)       // 74240
// per-warp weight rings: 4 warps x 4 stages x [16 c][32 f] fp32 (2048 B)
#define WSTAGE_BYTES 2048
#define WRING_BYTES  (NSTAGE * WSTAGE_BYTES)   // 8192 per warp
#define WT_OFF       PATCH_BYTES
#define SMEM_TOTAL   (WT_OFF + 4 * WRING_BYTES)   // 107008

// scratch: x transposed to [B][H*W][C]
__device__ float g_xt[(size_t)BATCH * LL * CIN];

// ---------------- helpers ----------------
__device__ __forceinline__ uint32_t swz(uint32_t o) { return o ^ ((o >> 3) & 0x70); }

__device__ __forceinline__ uint32_t cvt_tf32(float v) {
    uint32_t t;
    asm("cvt.rna.tf32.f32 %0, %1;" : "=r"(t) : "f"(v));
    return t;
}
__device__ __forceinline__ uint32_t tf32r(uint32_t bits) {
    uint32_t t;
    asm("cvt.rna.tf32.f32 %0, %1;" : "=r"(t) : "f"(__uint_as_float(bits)));
    return t;
}

__device__ __forceinline__ void sts32(uint32_t a, uint32_t v) {
    asm volatile("st.shared.b32 [%0], %1;" :: "r"(a), "r"(v) : "memory");
}

__device__ __forceinline__ void cp_async16(uint32_t smem_addr, const void* gmem_ptr) {
    asm volatile("cp.async.cg.shared.global [%0], [%1], 16;\n"
                 :: "r"(smem_addr), "l"(gmem_ptr));
}

__device__ __forceinline__ void ldsm_x4(uint32_t addr, uint32_t& r0, uint32_t& r1,
                                        uint32_t& r2, uint32_t& r3) {
    asm volatile("ldmatrix.sync.aligned.m8n8.x4.shared.b16 {%0,%1,%2,%3}, [%4];"
                 : "=r"(r0), "=r"(r1), "=r"(r2), "=r"(r3) : "r"(addr));
}

__device__ __forceinline__ void mma_tf32(float* d, const uint32_t* a, const uint32_t* b) {
    asm volatile("mma.sync.aligned.m16n8k8.row.col.f32.tf32.tf32.f32 "
                 "{%0,%1,%2,%3}, {%4,%5,%6,%7}, {%8,%9}, {%0,%1,%2,%3};"
                 : "+f"(d[0]), "+f"(d[1]), "+f"(d[2]), "+f"(d[3])
                 : "r"(a[0]), "r"(a[1]), "r"(a[2]), "r"(a[3]),
                   "r"(b[0]), "r"(b[1]));
}

// ---------------- kernel 1: x NCHW -> NHWC transpose ----------------
__global__ void __launch_bounds__(256) transpose_x(const float* __restrict__ x) {
    __shared__ float tile[32][33];
    const int b  = blockIdx.z;
    const int c0 = blockIdx.y * 32;
    const int s0 = blockIdx.x * 32;
    const int tx = threadIdx.x & 31;
    const int ty = threadIdx.x >> 5;   // 0..7
    #pragma unroll
    for (int i = 0; i < 4; i++)
        tile[ty + 8 * i][tx] = x[((size_t)b * CIN + c0 + ty + 8 * i) * LL + s0 + tx];
    __syncthreads();
    #pragma unroll
    for (int i = 0; i < 4; i++)
        g_xt[((size_t)b * LL + s0 + ty + 8 * i) * CIN + c0 + tx] = tile[tx][ty + 8 * i];
}

// ---------------- kernel 2: per-location GEMM, barrier-free mainloop ----------------
__global__ void __launch_bounds__(NTHREADS, 2)
lc2d_mma(const float* __restrict__ w,
         const float* __restrict__ bias,
         float* __restrict__ out)
{
    extern __shared__ char smem[];
    const uint32_t sb = (uint32_t)__cvta_generic_to_shared(smem);

    const int tid  = threadIdx.x;
    const int lane = tid & 31;
    const int warp = tid >> 5;
    const int l    = blockIdx.x;
    const int oh   = l / WW;
    const int ow   = l - oh * WW;

    const float* wl = w + (size_t)l * (COUT * FEAT);

    // warp-private weight ring
    const uint32_t wring = sb + WT_OFF + (uint32_t)warp * WRING_BYTES;

    // cp.async mapping: this warp covers channels [16*warp, 16*warp+16)
    // lane -> row = lane>>1 (0..15), fsel = lane&1; 4x 16B per lane per chunk
    const int wrow = lane >> 1;
    const int fsel = lane & 1;
    const float* wg = wl + (size_t)(warp * 16 + wrow) * FEAT + 4 * fsel;   // + k*32 + 8j
    const uint32_t wsd = (uint32_t)wrow * 128 + (uint32_t)fsel * 16;        // + j*32 (pre-swz)

    // ---- prologue: issue chunks 0..2 into stages 0..2 (per-warp groups) ----
    #pragma unroll
    for (int k = 0; k < NSTAGE - 1; k++) {
        const uint32_t st = wring + (uint32_t)k * WSTAGE_BYTES;
        #pragma unroll
        for (int j = 0; j < 4; j++)
            cp_async16(st + swz(wsd + (uint32_t)j * 32), wg + k * 32 + 8 * j);
        asm volatile("cp.async.commit_group;\n");
    }

    // ---- stage patches from g_xt (NHWC): segment = (b, ki, kj), 16 thr/seg ----
    {
        const int pos = tid & 15;                 // cin group: cin = pos*4 + q
        for (int s = tid >> 4; s < BATCH * 9; s += 8) {
            int b  = s / 9;
            int rr = s - b * 9;                   // ki*3 + kj
            int ki = rr / 3, kj = rr - ki * 3;
            int h  = oh + ki - 1;
            int wq = ow + kj - 1;
            bool ok = ((unsigned)h < HH) & ((unsigned)wq < WW);
            float4 v = make_float4(0.f, 0.f, 0.f, 0.f);
            if (ok)
                v = *(const float4*)(g_xt + ((size_t)b * LL + h * WW + wq) * CIN + pos * 4);
            const uint32_t prow = sb + (uint32_t)b * PROW_BYTES;
            #pragma unroll
            for (int q = 0; q < 4; q++) {
                float val = (q == 0) ? v.x : (q == 1) ? v.y : (q == 2) ? v.z : v.w;
                int f = (pos * 4 + q) * 9 + rr;
                sts32(prow + (uint32_t)f * 4, cvt_tf32(val));
            }
        }
    }

    // ---- fragment addressing ----
    // A (weights): warp-private 16 rows; m16n8k8 A-frag via ldsm_x4
    const uint32_t a_row  = (uint32_t)(lane & 15);
    const uint32_t a_colq = (lane & 16) ? 16u : 0u;
    // B (patches): 32 batches = 2 ldsm_x4 per k-step
    const uint32_t b_row  = (uint32_t)((lane & 7) + ((lane & 16) ? 8 : 0));
    const uint32_t b_colq = ((lane >> 3) & 1) ? 16u : 0u;
    const uint32_t b_base = sb + b_row * PROW_BYTES + b_colq;   // rows 0-15; +16 rows via offset

    float acc[4][4];
    #pragma unroll
    for (int ni = 0; ni < 4; ni++)
        #pragma unroll
        for (int q = 0; q < 4; q++) acc[ni][q] = 0.0f;

    __syncthreads();   // patch tile ready (only CTA-wide sync in the kernel)

    // ---- main loop: NO barriers; per-warp ring + per-warp wait_group ----
    for (int k = 0; k < NCHUNK; k++) {
        if (k + NSTAGE - 1 < NCHUNK) {
            // issue chunk k+3 into stage (k+3)&3 (WAR safe: own warp already
            // consumed that stage's data into registers in iteration k-1)
            const uint32_t st = wring + (uint32_t)((k + NSTAGE - 1) & (NSTAGE - 1)) * WSTAGE_BYTES;
            const int f0 = (k + NSTAGE - 1) * 32;
            #pragma unroll
            for (int j = 0; j < 4; j++)
                cp_async16(st + swz(wsd + (uint32_t)j * 32), wg + f0 + 8 * j);
            asm volatile("cp.async.commit_group;\n");
            asm volatile("cp.async.wait_group 3;\n");   // chunk k arrived
        } else {
            const int rem = NCHUNK - 1 - k;             // 2, 1, 0
            if (rem == 2)      asm volatile("cp.async.wait_group 2;\n");
            else if (rem == 1) asm volatile("cp.async.wait_group 1;\n");
            else               asm volatile("cp.async.wait_group 0;\n");
        }

        const uint32_t wt = wring + (uint32_t)(k & (NSTAGE - 1)) * WSTAGE_BYTES;
        #pragma unroll
        for (int ks = 0; ks < 4; ks++) {
            uint32_t a0[4], bf0[4], bf1[4];
            ldsm_x4(wt + swz(a_row * 128 + (uint32_t)ks * 32 + a_colq),
                    a0[0], a0[1], a0[2], a0[3]);
            const uint32_t bcol = (uint32_t)(k * 128 + ks * 32);
            ldsm_x4(b_base + bcol,                          bf0[0], bf0[1], bf0[2], bf0[3]);
            ldsm_x4(b_base + 16 * PROW_BYTES + bcol,        bf1[0], bf1[1], bf1[2], bf1[3]);
            #pragma unroll
            for (int q = 0; q < 4; q++) a0[q] = tf32r(a0[q]);
            mma_tf32(acc[0], a0, bf0);        // batches 0-7
            mma_tf32(acc[1], a0, bf0 + 2);    // batches 8-15
            mma_tf32(acc[2], a0, bf1);        // batches 16-23
            mma_tf32(acc[3], a0, bf1 + 2);    // batches 24-31
        }
    }

    // ---- epilogue ----
    // d mapping: c0:(g,2t) c1:(g,2t+1) c2:(g+8,2t) c3:(g+8,2t+1); g=lane>>2, t=lane&3
    const int g  = lane >> 2;
    const int t  = lane & 3;
    const int chA = warp * 16 + g;
    const float* bl = bias + (size_t)l * COUT;
    const float bvA = bl[chA];
    const float bvB = bl[chA + 8];
    #pragma unroll
    for (int ni = 0; ni < 4; ni++) {
        const int b0 = ni * 8 + 2 * t;
        out[((size_t)((b0    ) * COUT) + chA    ) * LL + l] = acc[ni][0] + bvA;
        out[((size_t)((b0 + 1) * COUT) + chA    ) * LL + l] = acc[ni][1] + bvA;
        out[((size_t)((b0    ) * COUT) + chA + 8) * LL + l] = acc[ni][2] + bvB;
        out[((size_t)((b0 + 1) * COUT) + chA + 8) * LL + l] = acc[ni][3] + bvB;
    }
}

extern "C" void kernel_launch(void* const* d_in, const int* in_sizes, int n_in,
                              void* d_out, int out_size)
{
    const float* x    = (const float*)d_in[0];   // [32,64,56,56]
    const float* w    = (const float*)d_in[1];   // [3136,64,576]
    const float* bias = (const float*)d_in[2];   // [3136,64]
    float* out        = (float*)d_out;           // [32,64,56,56]

    transpose_x<<<dim3(LL / 32, CIN / 32, BATCH), 256>>>(x);

    cudaFuncSetAttribute(lc2d_mma, cudaFuncAttributeMaxDynamicSharedMemorySize, SMEM_TOTAL);
    lc2d_mma<<<LL, NTHREADS, SMEM_TOTAL>>>(w, bias, out);
}